// round 4
// baseline (speedup 1.0000x reference)
#include <cuda_runtime.h>
#include <cstdint>
#include <cstddef>

#define Bn    32
#define Sn    512
#define Dn    1024
#define DROP  128
#define KEEP  384
#define NROW  (Bn*DROP)      // 4096 rows of lossmat
#define NCOL  (Bn*Sn)        // 16384 cols of lossmat
#define CBN   (NCOL/128)     // 128 column blocks

// ---------------- scratch (device globals; no runtime allocation) ----------------
__device__ float g_A[(size_t)NROW*Dn];        // 16 MB: TF32-rounded predictions
__device__ float g_Bm[(size_t)NCOL*Dn];       // 64 MB: TF32-rounded keys
__device__ float g_pMax[(size_t)NROW*CBN];    // per (row, colblock) max
__device__ float g_pSum[(size_t)NROW*CBN];    // per (row, colblock) sum exp(l - localmax)
__device__ int   g_pIdx[(size_t)NROW*CBN];    // per (row, colblock) argmax (global col)
__device__ int   g_target[NROW];              // absolute position b*Sn + drop
__device__ int   g_keep[Bn*KEEP];             // absolute position b*Sn + keep
__device__ int   g_is64;                      // 1 if index tensors are int64, else int32
__device__ float g_xe;
__device__ float g_mseS;
__device__ float g_acc;

__device__ __forceinline__ float tf32r(float f) {
    unsigned u;
    asm("cvt.rna.tf32.f32 %0, %1;" : "=r"(u) : "f"(f));
    return __uint_as_float(u);
}

// ---------------- kernel: zero accumulators ----------------
__global__ void k_zero() {
    if (threadIdx.x == 0) { g_xe = 0.f; g_mseS = 0.f; g_acc = 0.f; }
}

// ---------------- kernel: detect index dtype ----------------
// If the buffer truly holds int64 values in [0, 512), every high 32-bit word is 0.
// If it holds int32, the "high words" are other indices, almost surely nonzero somewhere.
__global__ void k_detect(const int* __restrict__ drop_as_i32) {
    if (threadIdx.x == 0 && blockIdx.x == 0) {
        int any = 0;
        #pragma unroll 4
        for (int i = 0; i < 64; i++) any |= drop_as_i32[2 * i + 1];
        g_is64 = (any == 0) ? 1 : 0;
    }
}

// ---------------- kernel: convert indices to absolute int positions ----------------
__global__ void k_prep(const void* __restrict__ drop, const void* __restrict__ keep) {
    int i = blockIdx.x * blockDim.x + threadIdx.x;
    const int is64 = g_is64;
    if (i < Bn * DROP) {
        int b = i / DROP;
        int v = is64 ? (int)((const long long*)drop)[i] : ((const int*)drop)[i];
        g_target[i] = b * Sn + v;
    }
    if (i < Bn * KEEP) {
        int b = i / KEEP;
        int v = is64 ? (int)((const long long*)keep)[i] : ((const int*)keep)[i];
        g_keep[i] = b * Sn + v;
    }
}

// ---------------- kernel: gather predictions + TF32 round ----------------
__global__ void k_gather(const float* __restrict__ out_seq) {
    int n = blockIdx.x;                  // 0..4095
    int t = threadIdx.x;                 // 0..255
    int tgt = g_target[n];
    const float4* src = reinterpret_cast<const float4*>(out_seq) + (size_t)tgt * (Dn / 4);
    float4* dst = reinterpret_cast<float4*>(g_A) + (size_t)n * (Dn / 4);
    float4 v = src[t];
    v.x = tf32r(v.x); v.y = tf32r(v.y); v.z = tf32r(v.z); v.w = tf32r(v.w);
    dst[t] = v;
}

// ---------------- kernel: TF32-round keys ----------------
__global__ void k_convB(const float* __restrict__ in_seq) {
    const float4* src = reinterpret_cast<const float4*>(in_seq);
    float4* dst = reinterpret_cast<float4*>(g_Bm);
    size_t total = (size_t)NCOL * (Dn / 4);
    for (size_t i = (size_t)blockIdx.x * blockDim.x + threadIdx.x; i < total;
         i += (size_t)gridDim.x * blockDim.x) {
        float4 v = src[i];
        v.x = tf32r(v.x); v.y = tf32r(v.y); v.z = tf32r(v.z); v.w = tf32r(v.w);
        dst[i] = v;
    }
}

// ---------------- kernel: TF32 GEMM (128x128 tile) + fused partial softmax ----------------
__global__ __launch_bounds__(256, 2) void k_gemm() {
    // 16B alignment is REQUIRED for cp.async destinations.
    __shared__ __align__(16) float sA[2][128][20]; // stride 20 floats: conflict-free frag loads
    __shared__ __align__(16) float sB[2][128][20];
    __shared__ float redV[128][4];
    __shared__ int   redI[128][4];
    __shared__ float rowMax[128];

    const int tid  = threadIdx.x;
    const int lane = tid & 31, warp = tid >> 5;
    const int g    = lane >> 2, tig = lane & 3;
    const int wm   = warp >> 2, wn = warp & 3;      // 2 x 4 warp grid (64x32 per warp)
    const int cb   = blockIdx.x;                    // column block (128 cols)
    const size_t rowbase = (size_t)blockIdx.y * 128;
    const size_t colbase = (size_t)cb * 128;

    float acc[4][4][4];
    #pragma unroll
    for (int a = 0; a < 4; a++)
        #pragma unroll
        for (int bb = 0; bb < 4; bb++)
            #pragma unroll
            for (int c = 0; c < 4; c++) acc[a][bb][c] = 0.f;

    auto issue = [&](int kt, int bufw) {
        #pragma unroll
        for (int i = 0; i < 4; i++) {
            int id = tid + 256 * i;                 // 1024 float4 per tile: 512 A + 512 B
            const float* src;
            float* dst;
            if (id < 512) {
                int r = id >> 2, c4 = id & 3;
                src = g_A + (rowbase + r) * Dn + kt * 16 + c4 * 4;
                dst = &sA[bufw][r][c4 * 4];
            } else {
                int id2 = id - 512;
                int r = id2 >> 2, c4 = id2 & 3;
                src = g_Bm + (colbase + r) * Dn + kt * 16 + c4 * 4;
                dst = &sB[bufw][r][c4 * 4];
            }
            unsigned sa = (unsigned)__cvta_generic_to_shared(dst);
            asm volatile("cp.async.cg.shared.global [%0], [%1], 16;" :: "r"(sa), "l"(src));
        }
        asm volatile("cp.async.commit_group;");
    };

    issue(0, 0);
    int buf = 0;
    for (int kt = 0; kt < 64; kt++) {               // K = 1024 = 64 * 16
        asm volatile("cp.async.wait_group 0;");
        __syncthreads();
        if (kt + 1 < 64) issue(kt + 1, buf ^ 1);
        #pragma unroll
        for (int ks = 0; ks < 2; ks++) {            // two k8 steps per 16-wide tile
            const int c0 = ks * 8 + tig;
            unsigned af[4][4];
            #pragma unroll
            for (int mf = 0; mf < 4; mf++) {
                int ar = wm * 64 + mf * 16;
                af[mf][0] = __float_as_uint(sA[buf][ar + g    ][c0]);
                af[mf][1] = __float_as_uint(sA[buf][ar + g + 8][c0]);
                af[mf][2] = __float_as_uint(sA[buf][ar + g    ][c0 + 4]);
                af[mf][3] = __float_as_uint(sA[buf][ar + g + 8][c0 + 4]);
            }
            #pragma unroll
            for (int nf = 0; nf < 4; nf++) {
                int bc = wn * 32 + nf * 8 + g;
                unsigned b0 = __float_as_uint(sB[buf][bc][c0]);
                unsigned b1 = __float_as_uint(sB[buf][bc][c0 + 4]);
                #pragma unroll
                for (int mf = 0; mf < 4; mf++) {
                    asm volatile(
                        "mma.sync.aligned.m16n8k8.row.col.f32.tf32.tf32.f32 "
                        "{%0,%1,%2,%3}, {%4,%5,%6,%7}, {%8,%9}, {%0,%1,%2,%3};"
                        : "+f"(acc[mf][nf][0]), "+f"(acc[mf][nf][1]),
                          "+f"(acc[mf][nf][2]), "+f"(acc[mf][nf][3])
                        : "r"(af[mf][0]), "r"(af[mf][1]), "r"(af[mf][2]), "r"(af[mf][3]),
                          "r"(b0), "r"(b1));
                }
            }
        }
        buf ^= 1;
    }

    // ---- fused epilogue: per-row (max, argmax), then sum exp(l - rowmax) ----
    #pragma unroll
    for (int mf = 0; mf < 4; mf++) {
        #pragma unroll
        for (int h = 0; h < 2; h++) {
            float m = -3.4e38f; int mi = 0x7fffffff;
            #pragma unroll
            for (int nf = 0; nf < 4; nf++)
                #pragma unroll
                for (int q = 0; q < 2; q++) {
                    float v = acc[mf][nf][h * 2 + q];
                    int col = wn * 32 + nf * 8 + tig * 2 + q;
                    if (v > m || (v == m && col < mi)) { m = v; mi = col; }
                }
            #pragma unroll
            for (int off = 1; off < 4; off <<= 1) {     // reduce across the 4 lanes of a group
                float vm = __shfl_xor_sync(0xffffffffu, m, off);
                int   vi = __shfl_xor_sync(0xffffffffu, mi, off);
                if (vm > m || (vm == m && vi < mi)) { m = vm; mi = vi; }
            }
            int rloc = wm * 64 + mf * 16 + g + h * 8;
            if (tig == 0) { redV[rloc][wn] = m; redI[rloc][wn] = mi; }
        }
    }
    __syncthreads();
    if (tid < 128) {
        float m = redV[tid][0]; int mi = redI[tid][0];
        #pragma unroll
        for (int w = 1; w < 4; w++) {
            float v = redV[tid][w]; int i = redI[tid][w];
            if (v > m || (v == m && i < mi)) { m = v; mi = i; }
        }
        rowMax[tid] = m;
        size_t grow = rowbase + tid;
        g_pMax[grow * CBN + cb] = m;
        g_pIdx[grow * CBN + cb] = (int)colbase + mi;
    }
    __syncthreads();
    #pragma unroll
    for (int mf = 0; mf < 4; mf++) {
        #pragma unroll
        for (int h = 0; h < 2; h++) {
            int rloc = wm * 64 + mf * 16 + g + h * 8;
            float M = rowMax[rloc];
            float s = 0.f;
            #pragma unroll
            for (int nf = 0; nf < 4; nf++)
                #pragma unroll
                for (int q = 0; q < 2; q++)
                    s += __expf(acc[mf][nf][h * 2 + q] - M);
            s += __shfl_xor_sync(0xffffffffu, s, 1);
            s += __shfl_xor_sync(0xffffffffu, s, 2);
            if (tig == 0) redV[rloc][wn] = s;
        }
    }
    __syncthreads();
    if (tid < 128) {
        float s = redV[tid][0] + redV[tid][1] + redV[tid][2] + redV[tid][3];
        g_pSum[(rowbase + tid) * CBN + cb] = s;
    }
}

// ---------------- kernel: combine partials per row + fp32 target logit + xe/acc ----------------
__global__ void k_combine(const float* __restrict__ in_seq,
                          const float* __restrict__ out_seq) {
    int n = blockIdx.x * 8 + (threadIdx.x >> 5);     // one warp per row
    int lane = threadIdx.x & 31;

    float m = -3.4e38f; int mi = 0x7fffffff;
    for (int j = lane; j < CBN; j += 32) {
        float v = g_pMax[(size_t)n * CBN + j];
        int   i = g_pIdx[(size_t)n * CBN + j];
        if (v > m || (v == m && i < mi)) { m = v; mi = i; }
    }
    #pragma unroll
    for (int off = 16; off; off >>= 1) {
        float vm = __shfl_xor_sync(0xffffffffu, m, off);
        int   vi = __shfl_xor_sync(0xffffffffu, mi, off);
        if (vm > m || (vm == m && vi < mi)) { m = vm; mi = vi; }
    }
    float s = 0.f;
    for (int j = lane; j < CBN; j += 32)
        s += g_pSum[(size_t)n * CBN + j] * __expf(g_pMax[(size_t)n * CBN + j] - m);
    #pragma unroll
    for (int off = 16; off; off >>= 1) s += __shfl_xor_sync(0xffffffffu, s, off);

    int t = g_target[n];
    // target logit in full fp32: predictions[n] . keys[t]; both are row t of their tensors
    const float* pr = out_seq + (size_t)t * Dn;
    const float* ky = in_seq + (size_t)t * Dn;
    float dot = 0.f;
    for (int d = lane; d < Dn; d += 32) dot = fmaf(pr[d], ky[d], dot);
    #pragma unroll
    for (int off = 16; off; off >>= 1) dot += __shfl_xor_sync(0xffffffffu, dot, off);

    if (lane == 0) {
        atomicAdd(&g_xe, (m + logf(s)) - dot);
        if (mi == t) atomicAdd(&g_acc, 1.f);
    }
}

// ---------------- kernel: MSE over kept positions ----------------
__global__ void k_mse(const float* __restrict__ in_seq,
                      const float* __restrict__ out_seq) {
    const int TOT4 = Bn * KEEP * (Dn / 4);   // 3,145,728
    const float4* in4 = reinterpret_cast<const float4*>(in_seq);
    const float4* out4 = reinterpret_cast<const float4*>(out_seq);
    float accv = 0.f;
    for (int i = blockIdx.x * blockDim.x + threadIdx.x; i < TOT4;
         i += gridDim.x * blockDim.x) {
        int r = i >> 8;          // kept-row index in [0, Bn*KEEP)
        int d4 = i & 255;
        size_t off = (size_t)g_keep[r] * (Dn / 4) + d4;
        float4 x = in4[off], y = out4[off];
        float dx = x.x - y.x, dy = x.y - y.y, dz = x.z - y.z, dw = x.w - y.w;
        accv += dx * dx + dy * dy + dz * dz + dw * dw;
    }
    #pragma unroll
    for (int off = 16; off; off >>= 1) accv += __shfl_xor_sync(0xffffffffu, accv, off);
    __shared__ float sr[8];
    int lane = threadIdx.x & 31, warp = threadIdx.x >> 5;
    if (lane == 0) sr[warp] = accv;
    __syncthreads();
    if (threadIdx.x == 0) {
        float blocksum = 0.f;
        #pragma unroll
        for (int w = 0; w < 8; w++) blocksum += sr[w];
        atomicAdd(&g_mseS, blocksum);
    }
}

// ---------------- kernel: finalize ----------------
__global__ void k_final(float* __restrict__ out) {
    float xe  = g_xe * (1.f / NROW);
    float mse = g_mseS * (1.f / ((float)Bn * KEEP * Dn));
    float acc = g_acc * (100.f / NROW);
    out[0] = xe + mse;
    out[1] = xe;
    out[2] = mse;
    out[3] = acc;
}

// ---------------- launch ----------------
extern "C" void kernel_launch(void* const* d_in, const int* in_sizes, int n_in,
                              void* d_out, int out_size) {
    const float* in_seq  = (const float*)d_in[0];
    const float* out_seq = (const float*)d_in[1];
    const void*  drop    = d_in[2];
    const void*  keep    = d_in[3];
    float* out = (float*)d_out;

    k_zero<<<1, 32>>>();
    k_detect<<<1, 32>>>((const int*)drop);
    k_prep<<<(Bn * KEEP + 255) / 256, 256>>>(drop, keep);
    k_gather<<<NROW, 256>>>(out_seq);
    k_convB<<<4096, 256>>>(in_seq);
    dim3 gg(CBN, NROW / 128);                 // (128, 32)
    k_gemm<<<gg, 256>>>();
    k_combine<<<NROW / 8, 256>>>(in_seq, out_seq);
    k_mse<<<2048, 256>>>(in_seq, out_seq);
    k_final<<<1, 1>>>(out);
}

// round 6
// speedup vs baseline: 1.2836x; 1.2836x over previous
#include <cuda_runtime.h>
#include <cstdint>
#include <cstddef>

#define Bn    32
#define Sn    512
#define Dn    1024
#define DROP  128
#define KEEP  384
#define NROW  (Bn*DROP)      // 4096 rows of lossmat
#define NCOL  (Bn*Sn)        // 16384 cols of lossmat
#define CBg   64             // column blocks of 256

// ---------------- scratch (device globals; no runtime allocation) ----------------
// Fragment-packed operands:
// A2: per mtile(128 rows): [kblk(128)][mblk(8)][lane(32)][reg(4)]   (16 MB)
// B2: per ctile(256 cols): [kblk(128)][npair(16)][lane(32)][reg(4)] (64 MB)
__device__ float g_A2[(size_t)NROW*Dn];
__device__ float g_B2[(size_t)NCOL*Dn];
__device__ float g_pMax[(size_t)NROW*CBg];
__device__ float g_pSum[(size_t)NROW*CBg];
__device__ int   g_pIdx[(size_t)NROW*CBg];
__device__ int   g_target[NROW];              // absolute position b*Sn + drop
__device__ int   g_keep[Bn*KEEP];             // absolute position b*Sn + keep
__device__ int   g_is64;
__device__ float g_xe;
__device__ float g_mseS;
__device__ float g_acc;

__device__ __forceinline__ float tf32r(float f) {
    unsigned u;
    asm("cvt.rna.tf32.f32 %0, %1;" : "=r"(u) : "f"(f));
    return __uint_as_float(u);
}

// ---------------- small kernels ----------------
__global__ void k_zero() {
    if (threadIdx.x == 0) { g_xe = 0.f; g_mseS = 0.f; g_acc = 0.f; }
}

__global__ void k_detect(const int* __restrict__ drop_as_i32) {
    if (threadIdx.x == 0 && blockIdx.x == 0) {
        int any = 0;
        #pragma unroll 4
        for (int i = 0; i < 64; i++) any |= drop_as_i32[2 * i + 1];
        g_is64 = (any == 0) ? 1 : 0;
    }
}

__global__ void k_prep(const void* __restrict__ drop, const void* __restrict__ keep) {
    int i = blockIdx.x * blockDim.x + threadIdx.x;
    const int is64 = g_is64;
    if (i < Bn * DROP) {
        int b = i / DROP;
        int v = is64 ? (int)((const long long*)drop)[i] : ((const int*)drop)[i];
        g_target[i] = b * Sn + v;
    }
    if (i < Bn * KEEP) {
        int b = i / KEEP;
        int v = is64 ? (int)((const long long*)keep)[i] : ((const int*)keep)[i];
        g_keep[i] = b * Sn + v;
    }
}

// gather predictions -> fragment-packed A2
// A frag (m16n8k8): lane=(g*4+tig): reg0=(g,tig) reg1=(g+8,tig) reg2=(g,tig+4) reg3=(g+8,tig+4)
__global__ void k_gather(const float* __restrict__ out_seq) {
    int n = blockIdx.x;                   // global row 0..4095
    int t = threadIdx.x;                  // handles k = 4t..4t+3
    int tgt = g_target[n];
    const float4* src = reinterpret_cast<const float4*>(out_seq) + (size_t)tgt * (Dn / 4);
    float4 v = src[t];
    float vv[4] = { tf32r(v.x), tf32r(v.y), tf32r(v.z), tf32r(v.w) };

    int mtile = n >> 7, mloc = n & 127;
    int mblk = mloc >> 4, r = mloc & 15, g = r & 7, hi = r >> 3;
    int k0 = t * 4;
    int kblk = k0 >> 3;
    int khalf = (k0 >> 2) & 1;            // = t&1
    size_t base = (size_t)mtile * ((size_t)Dn * 128) + (size_t)kblk * 1024 + (size_t)mblk * 128;
    int reg = hi + 2 * khalf;
    #pragma unroll
    for (int j = 0; j < 4; j++) {         // tig = j
        int lane = g * 4 + j;
        g_A2[base + lane * 4 + reg] = vv[j];
    }
}

// keys -> fragment-packed B2
// B frag: lane=(g*4+tig): reg = sub*2 + khalf, value (n = nblk*8+g, k)
__global__ void k_convB(const float* __restrict__ in_seq) {
    int c = blockIdx.x;                   // global col (key row) 0..16383
    int t = threadIdx.x;
    const float4* src = reinterpret_cast<const float4*>(in_seq) + (size_t)c * (Dn / 4);
    float4 v = src[t];
    float vv[4] = { tf32r(v.x), tf32r(v.y), tf32r(v.z), tf32r(v.w) };

    int ctile = c >> 8, nloc = c & 255;
    int nblk = nloc >> 3, g = nloc & 7;
    int p = nblk >> 1, sub = nblk & 1;
    int k0 = t * 4;
    int kblk = k0 >> 3;
    int khalf = (k0 >> 2) & 1;
    size_t base = (size_t)ctile * ((size_t)Dn * 256) + (size_t)kblk * 2048 + (size_t)p * 128;
    int reg = sub * 2 + khalf;
    #pragma unroll
    for (int j = 0; j < 4; j++) {         // tig = j
        int lane = g * 4 + j;
        g_B2[base + lane * 4 + reg] = vv[j];
    }
}

// ---------------- TF32 mma.sync GEMM: 128(M) x 256(N) per CTA, BK=32, 2-stage ----------------
// smem (dynamic): A stages 2x16KB @0,@16K; B stages 2x32KB @32K,@64K. Total 96KB.
#define A_FOFF(b) ((b)*4096)              // float offsets
#define B_FOFF(b) (8192 + (b)*8192)
#define SM_TOTAL  98304

__global__ __launch_bounds__(256, 1) void k_gemm() {
    extern __shared__ float smem[];
    const int tid = threadIdx.x, wid = tid >> 5, lane = tid & 31;
    const int wm = wid >> 2, wn = wid & 3;        // 2(M) x 4(N) warps; warp tile 64x64
    const int mtile = blockIdx.y, ctile = blockIdx.x;

    const float* srcA = g_A2 + (size_t)mtile * ((size_t)Dn * 128);
    const float* srcB = g_B2 + (size_t)ctile * ((size_t)Dn * 256);

    float acc[4][8][4];
    #pragma unroll
    for (int a = 0; a < 4; a++)
        #pragma unroll
        for (int b = 0; b < 8; b++)
            #pragma unroll
            for (int cc = 0; cc < 4; cc++) acc[a][b][cc] = 0.f;

    auto issue = [&](int kt, int buf) {
        const float4* sa4 = reinterpret_cast<const float4*>(srcA + kt * 4096);
        const float4* sb4 = reinterpret_cast<const float4*>(srcB + kt * 8192);
        float4* da = reinterpret_cast<float4*>(smem + A_FOFF(buf));
        float4* db = reinterpret_cast<float4*>(smem + B_FOFF(buf));
        #pragma unroll
        for (int i = 0; i < 4; i++) {
            unsigned d = (unsigned)__cvta_generic_to_shared(da + tid + 256 * i);
            asm volatile("cp.async.cg.shared.global [%0], [%1], 16;"
                         :: "r"(d), "l"(sa4 + tid + 256 * i));
        }
        #pragma unroll
        for (int i = 0; i < 8; i++) {
            unsigned d = (unsigned)__cvta_generic_to_shared(db + tid + 256 * i);
            asm volatile("cp.async.cg.shared.global [%0], [%1], 16;"
                         :: "r"(d), "l"(sb4 + tid + 256 * i));
        }
        asm volatile("cp.async.commit_group;");
    };

    issue(0, 0);
    for (int it = 0; it < 32; ++it) {             // K = 1024 = 32 * 32
        int buf = it & 1;
        asm volatile("cp.async.wait_group 0;");
        __syncthreads();
        if (it + 1 < 32) issue(it + 1, buf ^ 1);

        const uint4* smA = reinterpret_cast<const uint4*>(smem + A_FOFF(buf));
        const uint4* smB = reinterpret_cast<const uint4*>(smem + B_FOFF(buf));
        #pragma unroll
        for (int kb = 0; kb < 4; ++kb) {
            uint4 av[4], bv[4];
            #pragma unroll
            for (int mf = 0; mf < 4; mf++)
                av[mf] = smA[(kb * 8 + wm * 4 + mf) * 32 + lane];
            #pragma unroll
            for (int p = 0; p < 4; p++)
                bv[p] = smB[(kb * 16 + wn * 4 + p) * 32 + lane];
            #pragma unroll
            for (int p = 0; p < 4; p++) {
                #pragma unroll
                for (int mf = 0; mf < 4; mf++) {
                    asm volatile(
                        "mma.sync.aligned.m16n8k8.row.col.f32.tf32.tf32.f32 "
                        "{%0,%1,%2,%3}, {%4,%5,%6,%7}, {%8,%9}, {%0,%1,%2,%3};"
                        : "+f"(acc[mf][2*p][0]), "+f"(acc[mf][2*p][1]),
                          "+f"(acc[mf][2*p][2]), "+f"(acc[mf][2*p][3])
                        : "r"(av[mf].x), "r"(av[mf].y), "r"(av[mf].z), "r"(av[mf].w),
                          "r"(bv[p].x), "r"(bv[p].y));
                    asm volatile(
                        "mma.sync.aligned.m16n8k8.row.col.f32.tf32.tf32.f32 "
                        "{%0,%1,%2,%3}, {%4,%5,%6,%7}, {%8,%9}, {%0,%1,%2,%3};"
                        : "+f"(acc[mf][2*p+1][0]), "+f"(acc[mf][2*p+1][1]),
                          "+f"(acc[mf][2*p+1][2]), "+f"(acc[mf][2*p+1][3])
                        : "r"(av[mf].x), "r"(av[mf].y), "r"(av[mf].z), "r"(av[mf].w),
                          "r"(bv[p].z), "r"(bv[p].w));
                }
            }
        }
    }
    __syncthreads();

    // ---- fused epilogue: per-(row, 256-col block) max/argmax/sumexp partials ----
    float* redV = smem;                   // [128][4]
    int*   redI = (int*)(smem + 512);     // [128][4]
    float* redS = smem + 1024;            // [128][4]
    float* rm   = smem + 1536;            // [128]
    const int g = lane >> 2, tig = lane & 3;

    #pragma unroll
    for (int mf = 0; mf < 4; mf++) {
        #pragma unroll
        for (int h = 0; h < 2; h++) {
            float m = -3.4e38f; int mi = 0x7fffffff;
            #pragma unroll
            for (int nf = 0; nf < 8; nf++)
                #pragma unroll
                for (int q = 0; q < 2; q++) {
                    float v = acc[mf][nf][h * 2 + q];
                    int col = wn * 64 + nf * 8 + tig * 2 + q;
                    if (v > m || (v == m && col < mi)) { m = v; mi = col; }
                }
            #pragma unroll
            for (int off = 1; off < 4; off <<= 1) {
                float vm = __shfl_xor_sync(0xffffffffu, m, off);
                int   vi = __shfl_xor_sync(0xffffffffu, mi, off);
                if (vm > m || (vm == m && vi < mi)) { m = vm; mi = vi; }
            }
            int rloc = wm * 64 + mf * 16 + h * 8 + g;
            if (tig == 0) { redV[rloc * 4 + wn] = m; redI[rloc * 4 + wn] = mi; }
        }
    }
    __syncthreads();
    if (tid < 128) {
        float m = redV[tid * 4]; int mi = redI[tid * 4];
        #pragma unroll
        for (int w = 1; w < 4; w++) {
            float v = redV[tid * 4 + w]; int i = redI[tid * 4 + w];
            if (v > m || (v == m && i < mi)) { m = v; mi = i; }
        }
        rm[tid] = m;
        size_t grow = (size_t)mtile * 128 + tid;
        g_pMax[grow * CBg + ctile] = m;
        g_pIdx[grow * CBg + ctile] = ctile * 256 + mi;
    }
    __syncthreads();
    #pragma unroll
    for (int mf = 0; mf < 4; mf++) {
        #pragma unroll
        for (int h = 0; h < 2; h++) {
            int rloc = wm * 64 + mf * 16 + h * 8 + g;
            float M = rm[rloc];
            float s = 0.f;
            #pragma unroll
            for (int nf = 0; nf < 8; nf++)
                #pragma unroll
                for (int q = 0; q < 2; q++)
                    s += __expf(acc[mf][nf][h * 2 + q] - M);
            s += __shfl_xor_sync(0xffffffffu, s, 1);
            s += __shfl_xor_sync(0xffffffffu, s, 2);
            if (tig == 0) redS[rloc * 4 + wn] = s;
        }
    }
    __syncthreads();
    if (tid < 128) {
        float s = redS[tid * 4] + redS[tid * 4 + 1] + redS[tid * 4 + 2] + redS[tid * 4 + 3];
        g_pSum[((size_t)mtile * 128 + tid) * CBg + ctile] = s;
    }
}

// ---------------- combine partials per row + fp32 target logit + xe/acc ----------------
__global__ void k_combine(const float* __restrict__ in_seq,
                          const float* __restrict__ out_seq) {
    int n = blockIdx.x * 8 + (threadIdx.x >> 5);     // one warp per row
    int lane = threadIdx.x & 31;

    float m = -3.4e38f; int mi = 0x7fffffff;
    #pragma unroll
    for (int j = lane; j < CBg; j += 32) {
        float v = g_pMax[(size_t)n * CBg + j];
        int   i = g_pIdx[(size_t)n * CBg + j];
        if (v > m || (v == m && i < mi)) { m = v; mi = i; }
    }
    #pragma unroll
    for (int off = 16; off; off >>= 1) {
        float vm = __shfl_xor_sync(0xffffffffu, m, off);
        int   vi = __shfl_xor_sync(0xffffffffu, mi, off);
        if (vm > m || (vm == m && vi < mi)) { m = vm; mi = vi; }
    }
    float s = 0.f;
    #pragma unroll
    for (int j = lane; j < CBg; j += 32)
        s += g_pSum[(size_t)n * CBg + j] * __expf(g_pMax[(size_t)n * CBg + j] - m);
    #pragma unroll
    for (int off = 16; off; off >>= 1) s += __shfl_xor_sync(0xffffffffu, s, off);

    int t = g_target[n];
    const float* pr = out_seq + (size_t)t * Dn;      // target logit in full fp32
    const float* ky = in_seq + (size_t)t * Dn;
    float dot = 0.f;
    for (int d = lane; d < Dn; d += 32) dot = fmaf(pr[d], ky[d], dot);
    #pragma unroll
    for (int off = 16; off; off >>= 1) dot += __shfl_xor_sync(0xffffffffu, dot, off);

    if (lane == 0) {
        atomicAdd(&g_xe, (m + logf(s)) - dot);
        if (mi == t) atomicAdd(&g_acc, 1.f);
    }
}

// ---------------- MSE over kept positions ----------------
__global__ void k_mse(const float* __restrict__ in_seq,
                      const float* __restrict__ out_seq) {
    const int TOT4 = Bn * KEEP * (Dn / 4);
    const float4* in4 = reinterpret_cast<const float4*>(in_seq);
    const float4* out4 = reinterpret_cast<const float4*>(out_seq);
    float accv = 0.f;
    for (int i = blockIdx.x * blockDim.x + threadIdx.x; i < TOT4;
         i += gridDim.x * blockDim.x) {
        int r = i >> 8;
        int d4 = i & 255;
        size_t off = (size_t)g_keep[r] * (Dn / 4) + d4;
        float4 x = in4[off], y = out4[off];
        float dx = x.x - y.x, dy = x.y - y.y, dz = x.z - y.z, dw = x.w - y.w;
        accv += dx * dx + dy * dy + dz * dz + dw * dw;
    }
    #pragma unroll
    for (int off = 16; off; off >>= 1) accv += __shfl_xor_sync(0xffffffffu, accv, off);
    __shared__ float sr[8];
    int lane = threadIdx.x & 31, warp = threadIdx.x >> 5;
    if (lane == 0) sr[warp] = accv;
    __syncthreads();
    if (threadIdx.x == 0) {
        float blocksum = 0.f;
        #pragma unroll
        for (int w = 0; w < 8; w++) blocksum += sr[w];
        atomicAdd(&g_mseS, blocksum);
    }
}

// ---------------- finalize ----------------
__global__ void k_final(float* __restrict__ out) {
    float xe  = g_xe * (1.f / NROW);
    float mse = g_mseS * (1.f / ((float)Bn * KEEP * Dn));
    float acc = g_acc * (100.f / NROW);
    out[0] = xe + mse;
    out[1] = xe;
    out[2] = mse;
    out[3] = acc;
}

// ---------------- launch ----------------
extern "C" void kernel_launch(void* const* d_in, const int* in_sizes, int n_in,
                              void* d_out, int out_size) {
    const float* in_seq  = (const float*)d_in[0];
    const float* out_seq = (const float*)d_in[1];
    const void*  drop    = d_in[2];
    const void*  keep    = d_in[3];
    float* out = (float*)d_out;

    cudaFuncSetAttribute(k_gemm, cudaFuncAttributeMaxDynamicSharedMemorySize, SM_TOTAL);

    k_zero<<<1, 32>>>();
    k_detect<<<1, 32>>>((const int*)drop);
    k_prep<<<(Bn * KEEP + 255) / 256, 256>>>(drop, keep);
    k_gather<<<NROW, 256>>>(out_seq);
    k_convB<<<NCOL, 256>>>(in_seq);
    dim3 gg(CBg, 32);                               // 64 coltiles x 32 rowtiles
    k_gemm<<<gg, 256, SM_TOTAL>>>();
    k_combine<<<NROW / 8, 256>>>(in_seq, out_seq);
    k_mse<<<2048, 256>>>(in_seq, out_seq);
    k_final<<<1, 1>>>(out);
}

// round 8
// speedup vs baseline: 3.1372x; 2.4440x over previous
#include <cuda_runtime.h>
#include <cuda_bf16.h>
#include <cstdint>
#include <cstddef>

#define Bn    32
#define Sn    512
#define Dn    1024
#define DROP  128
#define KEEP  384
#define NROW  4096           // B*DROP rows of lossmat
#define NCOL  16384          // B*S cols of lossmat
#define CBg   128            // column blocks of 128

// ---------------- scratch (device globals; no runtime allocation) ----------------
// bf16 fragment-packed operands for mma.m16n8k16.row.col:
// A2u: [kblk(64)][mblkG(256)][lane(32)][reg(4)]  (u32 = bf16x2)  -> 8 MB
// B2u: [kblk(64)][npairG(1024)][lane(32)][reg(4)]                -> 32 MB
__device__ unsigned g_A2u[(size_t)64*256*128];
__device__ unsigned g_B2u[(size_t)64*1024*128];
__device__ float g_pMax[(size_t)NROW*CBg];
__device__ float g_pSum[(size_t)NROW*CBg];
__device__ int   g_pIdx[(size_t)NROW*CBg];
__device__ int   g_target[NROW];              // absolute position b*Sn + drop
__device__ int   g_keep[Bn*KEEP];             // absolute position b*Sn + keep
__device__ int   g_is64;
__device__ float g_xe;
__device__ float g_mseS;
__device__ float g_acc;

__device__ __forceinline__ unsigned pk_bf2(float lo, float hi) {
    __nv_bfloat162 h = __floats2bfloat162_rn(lo, hi);   // .x = lo (low 16 bits)
    return *reinterpret_cast<unsigned*>(&h);
}

// ---------------- small kernels ----------------
__global__ void k_zero() {
    if (threadIdx.x == 0) { g_xe = 0.f; g_mseS = 0.f; g_acc = 0.f; }
}

__global__ void k_detect(const int* __restrict__ drop_as_i32) {
    if (threadIdx.x == 0 && blockIdx.x == 0) {
        int any = 0;
        #pragma unroll 4
        for (int i = 0; i < 64; i++) any |= drop_as_i32[2 * i + 1];
        g_is64 = (any == 0) ? 1 : 0;
    }
}

__global__ void k_prep(const void* __restrict__ drop, const void* __restrict__ keep) {
    int i = blockIdx.x * blockDim.x + threadIdx.x;
    const int is64 = g_is64;
    if (i < Bn * DROP) {
        int b = i / DROP;
        int v = is64 ? (int)((const long long*)drop)[i] : ((const int*)drop)[i];
        g_target[i] = b * Sn + v;
    }
    if (i < Bn * KEEP) {
        int b = i / KEEP;
        int v = is64 ? (int)((const long long*)keep)[i] : ((const int*)keep)[i];
        g_keep[i] = b * Sn + v;
    }
}

// gather predictions -> bf16 fragment-packed A2u
// A frag (m16n8k16): lane=g*4+tig: a0={(g,2t),(g,2t+1)} a1=row g+8; a2/a3 = cols+8
__global__ void k_gather(const float* __restrict__ out_seq) {
    int n = blockIdx.x;                   // row 0..4095
    int t = threadIdx.x;                  // k = 4t..4t+3
    int tgt = g_target[n];
    float4 v = reinterpret_cast<const float4*>(out_seq)[(size_t)tgt * (Dn / 4) + t];
    unsigned p0 = pk_bf2(v.x, v.y), p1 = pk_bf2(v.z, v.w);

    int k0 = 4 * t, kblk = k0 >> 4, kin = k0 & 15;
    int mblkG = n >> 4, r = n & 15, g = r & 7, hi = r >> 3;
    size_t base = ((size_t)kblk * 256 + mblkG) * 128;
    #pragma unroll
    for (int j = 0; j < 2; j++) {
        int kk = kin + 2 * j;
        int tig = (kk & 7) >> 1;
        int reg = hi + ((kk >= 8) ? 2 : 0);
        g_A2u[base + (g * 4 + tig) * 4 + reg] = j ? p1 : p0;
    }
}

// keys -> bf16 fragment-packed B2u
// B frag: lane=g*4+tig: b0={(2t,g),(2t+1,g)} b1=rows+8; npair packs 2 nblks into 4 regs
__global__ void k_convB(const float* __restrict__ in_seq) {
    int c = blockIdx.x;                   // key row (lossmat col) 0..16383
    int t = threadIdx.x;
    float4 v = reinterpret_cast<const float4*>(in_seq)[(size_t)c * (Dn / 4) + t];
    unsigned p0 = pk_bf2(v.x, v.y), p1 = pk_bf2(v.z, v.w);

    int k0 = 4 * t, kblk = k0 >> 4, kin = k0 & 15;
    int pG = c >> 4, sub = (c >> 3) & 1, g = c & 7;
    size_t base = ((size_t)kblk * 1024 + pG) * 128;
    #pragma unroll
    for (int j = 0; j < 2; j++) {
        int kk = kin + 2 * j;
        int tig = (kk & 7) >> 1;
        int reg = sub * 2 + ((kk >= 8) ? 1 : 0);
        g_B2u[base + (g * 4 + tig) * 4 + reg] = j ? p1 : p0;
    }
}

// ---------------- bf16 mma.sync GEMM: 256(M) x 128(N) per CTA, 16 warps, BK=32 ----------------
// smem: 2 stages x 1536 uint4 (stage: A 1024 u4, B 512 u4) = 48 KB
#define STG_U4 1536
#define SM_TOTAL (2*STG_U4*16)

__global__ __launch_bounds__(512, 1) void k_gemm() {
    extern __shared__ uint4 sm4[];
    const int tid = threadIdx.x, wid = tid >> 5, lane = tid & 31;
    const int wm = wid >> 2, wn = wid & 3;        // 4(M) x 4(N) warps; warp tile 64x32
    const int ct = blockIdx.x, mt = blockIdx.y;   // 128 coltiles x 16 rowtiles
    const uint4* gA4 = reinterpret_cast<const uint4*>(g_A2u);
    const uint4* gB4 = reinterpret_cast<const uint4*>(g_B2u);

    float acc[4][4][4];
    #pragma unroll
    for (int a = 0; a < 4; a++)
        #pragma unroll
        for (int b = 0; b < 4; b++)
            #pragma unroll
            for (int cc = 0; cc < 4; cc++) acc[a][b][cc] = 0.f;

    auto issue = [&](int kt, int buf) {
        int sbase = buf * STG_U4;
        #pragma unroll
        for (int j = 0; j < 3; j++) {
            int id = tid + 512 * j;               // 0..1535
            const uint4* src; int dst;
            if (id < 1024) {                      // A: 2 kb x 512 u4 (contiguous per kb)
                int kb = id >> 9, l = id & 511;
                src = gA4 + ((size_t)(kt * 2 + kb) * 256 + mt * 16) * 32 + l;
                dst = sbase + kb * 512 + l;
            } else {                              // B: 2 kb x 256 u4
                int id2 = id - 1024;
                int kb = id2 >> 8, l = id2 & 255;
                src = gB4 + ((size_t)(kt * 2 + kb) * 1024 + ct * 8) * 32 + l;
                dst = sbase + 1024 + kb * 256 + l;
            }
            unsigned d = (unsigned)__cvta_generic_to_shared(sm4 + dst);
            asm volatile("cp.async.cg.shared.global [%0], [%1], 16;" :: "r"(d), "l"(src));
        }
        asm volatile("cp.async.commit_group;");
    };

    issue(0, 0);
    for (int it = 0; it < 32; ++it) {             // K = 1024 = 32 * 32
        int buf = it & 1;
        asm volatile("cp.async.wait_group 0;");
        __syncthreads();
        if (it + 1 < 32) issue(it + 1, buf ^ 1);

        const uint4* sA = sm4 + buf * STG_U4;
        const uint4* sB = sA + 1024;
        #pragma unroll
        for (int kb = 0; kb < 2; ++kb) {
            uint4 av[4], bv[2];
            #pragma unroll
            for (int mf = 0; mf < 4; mf++)
                av[mf] = sA[(kb * 16 + wm * 4 + mf) * 32 + lane];
            #pragma unroll
            for (int p = 0; p < 2; p++)
                bv[p] = sB[(kb * 8 + wn * 2 + p) * 32 + lane];
            #pragma unroll
            for (int p = 0; p < 2; p++) {
                #pragma unroll
                for (int mf = 0; mf < 4; mf++) {
                    asm volatile(
                        "mma.sync.aligned.m16n8k16.row.col.f32.bf16.bf16.f32 "
                        "{%0,%1,%2,%3}, {%4,%5,%6,%7}, {%8,%9}, {%0,%1,%2,%3};"
                        : "+f"(acc[mf][2*p][0]), "+f"(acc[mf][2*p][1]),
                          "+f"(acc[mf][2*p][2]), "+f"(acc[mf][2*p][3])
                        : "r"(av[mf].x), "r"(av[mf].y), "r"(av[mf].z), "r"(av[mf].w),
                          "r"(bv[p].x), "r"(bv[p].y));
                    asm volatile(
                        "mma.sync.aligned.m16n8k16.row.col.f32.bf16.bf16.f32 "
                        "{%0,%1,%2,%3}, {%4,%5,%6,%7}, {%8,%9}, {%0,%1,%2,%3};"
                        : "+f"(acc[mf][2*p+1][0]), "+f"(acc[mf][2*p+1][1]),
                          "+f"(acc[mf][2*p+1][2]), "+f"(acc[mf][2*p+1][3])
                        : "r"(av[mf].x), "r"(av[mf].y), "r"(av[mf].z), "r"(av[mf].w),
                          "r"(bv[p].z), "r"(bv[p].w));
                }
            }
        }
    }
    __syncthreads();

    // ---- fused epilogue: per-(row, 128-col block) max/argmax/sumexp partials ----
    float* redV = (float*)sm4;            // [256][4]
    int*   redI = (int*)(redV + 1024);    // [256][4]
    float* redS = (float*)(redI + 1024);  // [256][4]
    float* rm   = redS + 1024;            // [256]
    const int g = lane >> 2, tig = lane & 3;

    #pragma unroll
    for (int mf = 0; mf < 4; mf++) {
        #pragma unroll
        for (int h = 0; h < 2; h++) {
            float m = -3.4e38f; int mi = 0x7fffffff;
            #pragma unroll
            for (int nn = 0; nn < 4; nn++)
                #pragma unroll
                for (int q = 0; q < 2; q++) {
                    float v = acc[mf][nn][h * 2 + q];
                    int col = wn * 32 + nn * 8 + tig * 2 + q;
                    if (v > m || (v == m && col < mi)) { m = v; mi = col; }
                }
            #pragma unroll
            for (int off = 1; off < 4; off <<= 1) {
                float vm = __shfl_xor_sync(0xffffffffu, m, off);
                int   vi = __shfl_xor_sync(0xffffffffu, mi, off);
                if (vm > m || (vm == m && vi < mi)) { m = vm; mi = vi; }
            }
            int rloc = wm * 64 + mf * 16 + h * 8 + g;
            if (tig == 0) { redV[rloc * 4 + wn] = m; redI[rloc * 4 + wn] = mi; }
        }
    }
    __syncthreads();
    if (tid < 256) {
        float m = redV[tid * 4]; int mi = redI[tid * 4];
        #pragma unroll
        for (int w = 1; w < 4; w++) {
            float v = redV[tid * 4 + w]; int i = redI[tid * 4 + w];
            if (v > m || (v == m && i < mi)) { m = v; mi = i; }
        }
        rm[tid] = m;
        size_t grow = (size_t)mt * 256 + tid;
        g_pMax[grow * CBg + ct] = m;
        g_pIdx[grow * CBg + ct] = ct * 128 + mi;
    }
    __syncthreads();
    #pragma unroll
    for (int mf = 0; mf < 4; mf++) {
        #pragma unroll
        for (int h = 0; h < 2; h++) {
            int rloc = wm * 64 + mf * 16 + h * 8 + g;
            float M = rm[rloc];
            float s = 0.f;
            #pragma unroll
            for (int nn = 0; nn < 4; nn++)
                #pragma unroll
                for (int q = 0; q < 2; q++)
                    s += __expf(acc[mf][nn][h * 2 + q] - M);
            s += __shfl_xor_sync(0xffffffffu, s, 1);
            s += __shfl_xor_sync(0xffffffffu, s, 2);
            if (tig == 0) redS[rloc * 4 + wn] = s;
        }
    }
    __syncthreads();
    if (tid < 256) {
        float s = redS[tid * 4] + redS[tid * 4 + 1] + redS[tid * 4 + 2] + redS[tid * 4 + 3];
        g_pSum[((size_t)mt * 256 + tid) * CBg + ct] = s;
    }
}

// ---------------- combine partials per row + fp32 target logit + xe/acc ----------------
__global__ void k_combine(const float* __restrict__ in_seq,
                          const float* __restrict__ out_seq) {
    int n = blockIdx.x * 8 + (threadIdx.x >> 5);     // one warp per row
    int lane = threadIdx.x & 31;

    float m = -3.4e38f; int mi = 0x7fffffff;
    #pragma unroll
    for (int j = lane; j < CBg; j += 32) {
        float v = g_pMax[(size_t)n * CBg + j];
        int   i = g_pIdx[(size_t)n * CBg + j];
        if (v > m || (v == m && i < mi)) { m = v; mi = i; }
    }
    #pragma unroll
    for (int off = 16; off; off >>= 1) {
        float vm = __shfl_xor_sync(0xffffffffu, m, off);
        int   vi = __shfl_xor_sync(0xffffffffu, mi, off);
        if (vm > m || (vm == m && vi < mi)) { m = vm; mi = vi; }
    }
    float s = 0.f;
    #pragma unroll
    for (int j = lane; j < CBg; j += 32)
        s += g_pSum[(size_t)n * CBg + j] * __expf(g_pMax[(size_t)n * CBg + j] - m);
    #pragma unroll
    for (int off = 16; off; off >>= 1) s += __shfl_xor_sync(0xffffffffu, s, off);

    int t = g_target[n];
    const float* pr = out_seq + (size_t)t * Dn;      // target logit in full fp32
    const float* ky = in_seq + (size_t)t * Dn;
    float dot = 0.f;
    for (int d = lane; d < Dn; d += 32) dot = fmaf(pr[d], ky[d], dot);
    #pragma unroll
    for (int off = 16; off; off >>= 1) dot += __shfl_xor_sync(0xffffffffu, dot, off);

    if (lane == 0) {
        atomicAdd(&g_xe, (m + logf(s)) - dot);
        if (mi == t) atomicAdd(&g_acc, 1.f);
    }
}

// ---------------- MSE over kept positions ----------------
__global__ void k_mse(const float* __restrict__ in_seq,
                      const float* __restrict__ out_seq) {
    const int TOT4 = Bn * KEEP * (Dn / 4);
    const float4* in4 = reinterpret_cast<const float4*>(in_seq);
    const float4* out4 = reinterpret_cast<const float4*>(out_seq);
    float accv = 0.f;
    for (int i = blockIdx.x * blockDim.x + threadIdx.x; i < TOT4;
         i += gridDim.x * blockDim.x) {
        int r = i >> 8;
        int d4 = i & 255;
        size_t off = (size_t)g_keep[r] * (Dn / 4) + d4;
        float4 x = in4[off], y = out4[off];
        float dx = x.x - y.x, dy = x.y - y.y, dz = x.z - y.z, dw = x.w - y.w;
        accv += dx * dx + dy * dy + dz * dz + dw * dw;
    }
    #pragma unroll
    for (int off = 16; off; off >>= 1) accv += __shfl_xor_sync(0xffffffffu, accv, off);
    __shared__ float sr[8];
    int lane = threadIdx.x & 31, warp = threadIdx.x >> 5;
    if (lane == 0) sr[warp] = accv;
    __syncthreads();
    if (threadIdx.x == 0) {
        float blocksum = 0.f;
        #pragma unroll
        for (int w = 0; w < 8; w++) blocksum += sr[w];
        atomicAdd(&g_mseS, blocksum);
    }
}

// ---------------- finalize ----------------
__global__ void k_final(float* __restrict__ out) {
    float xe  = g_xe * (1.f / NROW);
    float mse = g_mseS * (1.f / ((float)Bn * KEEP * Dn));
    float acc = g_acc * (100.f / NROW);
    out[0] = xe + mse;
    out[1] = xe;
    out[2] = mse;
    out[3] = acc;
}

// ---------------- launch ----------------
extern "C" void kernel_launch(void* const* d_in, const int* in_sizes, int n_in,
                              void* d_out, int out_size) {
    const float* in_seq  = (const float*)d_in[0];
    const float* out_seq = (const float*)d_in[1];
    const void*  drop    = d_in[2];
    const void*  keep    = d_in[3];
    float* out = (float*)d_out;

    cudaFuncSetAttribute(k_gemm, cudaFuncAttributeMaxDynamicSharedMemorySize, SM_TOTAL);

    k_zero<<<1, 32>>>();
    k_detect<<<1, 32>>>((const int*)drop);
    k_prep<<<(Bn * KEEP + 255) / 256, 256>>>(drop, keep);
    k_gather<<<NROW, 256>>>(out_seq);
    k_convB<<<NCOL, 256>>>(in_seq);
    dim3 gg(CBg, 16);                               // 128 coltiles x 16 rowtiles
    k_gemm<<<gg, 512, SM_TOTAL>>>();
    k_combine<<<NROW / 8, 256>>>(in_seq, out_seq);
    k_mse<<<2048, 256>>>(in_seq, out_seq);
    k_final<<<1, 1>>>(out);
}